// round 3
// baseline (speedup 1.0000x reference)
#include <cuda_runtime.h>
#include <cstdint>
#include <cstddef>

#define N_NODES 100000
#define N_EDGES_MAX 1600000
#define D 128
#define SLD 768            // scratch row: [h(0:128) | beta(128:256) | gamma(256:384) | skip(384:512) | beta_s(512:640) | gamma_s(640:768)]
#define NLAYERS 4

// ---------------- device scratch (no allocations allowed) ----------------
__device__ __align__(16) float g_scratch[(size_t)N_NODES * SLD];
__device__ __align__(16) float g_xbuf0[(size_t)N_NODES * D];
__device__ __align__(16) float g_xbuf1[(size_t)N_NODES * D];
__device__ int   g_deg[N_NODES];
__device__ int   g_off[N_NODES + 1];
__device__ int   g_cursor[N_NODES];
__device__ int   g_csr[N_EDGES_MAX];
__device__ int   g_bsum[128];
__device__ int   g_idx32;          // 1 => edge_index stored as int32, 0 => int64

// ---------------- edge index dtype detection ----------------
// JAX demotes int64->int32 when x64 is disabled (the default), so edge_index
// is most likely int32 despite the reference saying int64. Detect at runtime:
// interpret the first entries as int64; any value outside [0, N_NODES) proves
// the buffer is packed int32 pairs.
__global__ void k_detect(const void* __restrict__ ei, int E)
{
    const long long* p = (const long long*)ei;
    int n = E < 4096 ? E : 4096;
    int is32 = 0;
    for (int i = 0; i < n; i++) {
        long long v = p[i];
        if (v < 0 || v >= N_NODES) { is32 = 1; break; }
    }
    g_idx32 = is32;
}

__device__ __forceinline__ int load_edge(const void* ei, int idx, int mode)
{
    if (mode) return ((const int*)ei)[idx];
    return (int)((const long long*)ei)[idx];
}

// ---------------- f32x2 helpers (Blackwell packed fp32) ----------------
__device__ __forceinline__ void fma2(unsigned long long& d, unsigned long long a, unsigned long long b) {
    asm("fma.rn.f32x2 %0, %1, %2, %0;" : "+l"(d) : "l"(a), "l"(b));
}
__device__ __forceinline__ unsigned long long bcast2(float x) {
    unsigned long long r;
    asm("mov.b64 %0, {%1, %1};" : "=l"(r) : "f"(x));
    return r;
}
__device__ __forceinline__ float2 unpack2(unsigned long long v) {
    float2 r;
    asm("mov.b64 {%0, %1}, %2;" : "=f"(r.x), "=f"(r.y) : "l"(v));
    return r;
}

// ---------------- GEMM: C[M, colOff:colOff+N] (ld=SLD) = A[M,128] @ B[128,N] (+bias) ----------------
// BM=128, BN=64, BK=16, 256 threads, per-thread 8x4 micro-tile as 4 row-pairs x 4 cols (f32x2)
#define BM 128
#define BN 64
#define BK 16

__global__ __launch_bounds__(256, 2)
void gemm_kernel(const float* __restrict__ A, const float* __restrict__ B,
                 const float* __restrict__ bias, float* __restrict__ C,
                 int M, int N, int colOff)
{
    __shared__ float As[BK][BM + 4];   // transposed A tile, padded
    __shared__ float Bs[BK][BN];

    const int m0 = blockIdx.x * BM;
    const int n0 = blockIdx.y * BN;
    const int tid = threadIdx.x;
    const int tx = tid & 15;           // col group 0..15 -> cols tx*4..tx*4+3
    const int ty = tid >> 4;           // row group 0..15 -> rows ty*8..ty*8+7

    unsigned long long acc[4][4];
    #pragma unroll
    for (int i = 0; i < 4; i++)
        #pragma unroll
        for (int j = 0; j < 4; j++) acc[i][j] = 0ull;

    const float* Ablk = A + (size_t)m0 * D;

    for (int kt = 0; kt < D; kt += BK) {
        // ---- load A tile (128x16), store transposed As[k][row] ----
        #pragma unroll
        for (int r = 0; r < 2; r++) {
            int idx = tid + r * 256;           // 0..511 over 512 float4s
            int row = idx >> 2;                // 0..127
            int c4  = (idx & 3) * 4;           // 0,4,8,12
            float4 v = make_float4(0.f, 0.f, 0.f, 0.f);
            if (m0 + row < M)
                v = *(const float4*)(Ablk + (size_t)row * D + kt + c4);
            As[c4 + 0][row] = v.x;
            As[c4 + 1][row] = v.y;
            As[c4 + 2][row] = v.z;
            As[c4 + 3][row] = v.w;
        }
        // ---- load B tile (16x64) ----
        {
            int row = tid >> 4;                // 0..15
            int c4  = (tid & 15) * 4;          // 0..60
            float4 v = *(const float4*)(B + (size_t)(kt + row) * N + n0 + c4);
            *(float4*)&Bs[row][c4] = v;
        }
        __syncthreads();

        #pragma unroll
        for (int k = 0; k < BK; k++) {
            const float* arow = &As[k][ty * 8];
            unsigned long long ap[4];
            ap[0] = *(const unsigned long long*)(arow + 0);
            ap[1] = *(const unsigned long long*)(arow + 2);
            ap[2] = *(const unsigned long long*)(arow + 4);
            ap[3] = *(const unsigned long long*)(arow + 6);
            float4 bv = *(const float4*)&Bs[k][tx * 4];
            unsigned long long b0 = bcast2(bv.x), b1 = bcast2(bv.y),
                               b2 = bcast2(bv.z), b3 = bcast2(bv.w);
            #pragma unroll
            for (int ip = 0; ip < 4; ip++) {
                fma2(acc[ip][0], ap[ip], b0);
                fma2(acc[ip][1], ap[ip], b1);
                fma2(acc[ip][2], ap[ip], b2);
                fma2(acc[ip][3], ap[ip], b3);
            }
        }
        __syncthreads();
    }

    // ---- epilogue ----
    float bv0 = 0.f, bv1 = 0.f, bv2 = 0.f, bv3 = 0.f;
    if (bias) {
        float4 t = *(const float4*)(bias + n0 + tx * 4);
        bv0 = t.x; bv1 = t.y; bv2 = t.z; bv3 = t.w;
    }
    #pragma unroll
    for (int ip = 0; ip < 4; ip++) {
        float2 c0 = unpack2(acc[ip][0]);
        float2 c1 = unpack2(acc[ip][1]);
        float2 c2 = unpack2(acc[ip][2]);
        float2 c3 = unpack2(acc[ip][3]);
        int row = m0 + ty * 8 + ip * 2;
        float* cp = C + (size_t)row * SLD + colOff + n0 + tx * 4;
        if (row < M)
            *(float4*)cp = make_float4(c0.x + bv0, c1.x + bv1, c2.x + bv2, c3.x + bv3);
        if (row + 1 < M)
            *(float4*)(cp + SLD) = make_float4(c0.y + bv0, c1.y + bv1, c2.y + bv2, c3.y + bv3);
    }
}

// ---------------- graph setup kernels ----------------
__global__ void k_deg(const void* __restrict__ ei, int E)
{
    const int mode = g_idx32;
    for (int i = blockIdx.x * blockDim.x + threadIdx.x; i < E; i += gridDim.x * blockDim.x) {
        int d = load_edge(ei, E + i, mode);   // dst row
        atomicAdd(&g_deg[d], 1);
    }
}

__global__ void k_scan1()   // per-block sums of g_deg, 1024 per block
{
    __shared__ int s[1024];
    int tid = threadIdx.x;
    int i = blockIdx.x * 1024 + tid;
    s[tid] = (i < N_NODES) ? g_deg[i] : 0;
    __syncthreads();
    #pragma unroll
    for (int d = 512; d > 0; d >>= 1) {
        if (tid < d) s[tid] += s[tid + d];
        __syncthreads();
    }
    if (tid == 0) g_bsum[blockIdx.x] = s[0];
}

__global__ void k_scan2(int nb)   // tiny serial exclusive scan of block sums
{
    int run = 0;
    for (int b = 0; b < nb; b++) {
        int v = g_bsum[b];
        g_bsum[b] = run;
        run += v;
    }
    g_off[N_NODES] = run;
}

__global__ void k_scan3()   // block-level exclusive scan + base
{
    __shared__ int s[1024];
    int tid = threadIdx.x;
    int i = blockIdx.x * 1024 + tid;
    int v = (i < N_NODES) ? g_deg[i] : 0;
    s[tid] = v;
    __syncthreads();
    #pragma unroll
    for (int d = 1; d < 1024; d <<= 1) {
        int t = (tid >= d) ? s[tid - d] : 0;
        __syncthreads();
        s[tid] += t;
        __syncthreads();
    }
    int excl = s[tid] - v;
    int base = g_bsum[blockIdx.x];
    if (i < N_NODES) {
        g_off[i]    = base + excl;
        g_cursor[i] = base + excl;
    }
}

__global__ void k_scatter(const void* __restrict__ ei, int E)
{
    const int mode = g_idx32;
    for (int i = blockIdx.x * blockDim.x + threadIdx.x; i < E; i += gridDim.x * blockDim.x) {
        int d = load_edge(ei, E + i, mode);   // dst
        int s = load_edge(ei, i, mode);       // src
        int pos = atomicAdd(&g_cursor[d], 1);
        g_csr[pos] = s;
    }
}

// ---------------- fused edge aggregation + FiLM-skip epilogue ----------------
// one warp per dst node; lane handles 4 channels (float4); 2x unrolled gather
__global__ __launch_bounds__(256)
void edge_agg_kernel(const float* __restrict__ scratch, float* __restrict__ xout, int applyRelu)
{
    int warp = (blockIdx.x * blockDim.x + threadIdx.x) >> 5;
    int lane = threadIdx.x & 31;
    if (warp >= N_NODES) return;

    const float* base = scratch + (size_t)warp * SLD;
    const int c = lane * 4;

    float4 beta  = *(const float4*)(base + 128 + c);
    float4 gamma = *(const float4*)(base + 256 + c);

    const int s0 = g_off[warp], s1 = g_off[warp + 1];
    float4 acc0 = make_float4(0.f, 0.f, 0.f, 0.f);
    float4 acc1 = make_float4(0.f, 0.f, 0.f, 0.f);

    int i = s0;
    for (; i + 2 <= s1; i += 2) {
        int sA = g_csr[i];
        int sB = g_csr[i + 1];
        float4 hA = __ldg((const float4*)(scratch + (size_t)sA * SLD + c));
        float4 hB = __ldg((const float4*)(scratch + (size_t)sB * SLD + c));
        acc0.x += fmaxf(fmaf(gamma.x, hA.x, beta.x), 0.f);
        acc0.y += fmaxf(fmaf(gamma.y, hA.y, beta.y), 0.f);
        acc0.z += fmaxf(fmaf(gamma.z, hA.z, beta.z), 0.f);
        acc0.w += fmaxf(fmaf(gamma.w, hA.w, beta.w), 0.f);
        acc1.x += fmaxf(fmaf(gamma.x, hB.x, beta.x), 0.f);
        acc1.y += fmaxf(fmaf(gamma.y, hB.y, beta.y), 0.f);
        acc1.z += fmaxf(fmaf(gamma.z, hB.z, beta.z), 0.f);
        acc1.w += fmaxf(fmaf(gamma.w, hB.w, beta.w), 0.f);
    }
    if (i < s1) {
        int sA = g_csr[i];
        float4 hA = __ldg((const float4*)(scratch + (size_t)sA * SLD + c));
        acc0.x += fmaxf(fmaf(gamma.x, hA.x, beta.x), 0.f);
        acc0.y += fmaxf(fmaf(gamma.y, hA.y, beta.y), 0.f);
        acc0.z += fmaxf(fmaf(gamma.z, hA.z, beta.z), 0.f);
        acc0.w += fmaxf(fmaf(gamma.w, hA.w, beta.w), 0.f);
    }
    float4 acc = make_float4(acc0.x + acc1.x, acc0.y + acc1.y,
                             acc0.z + acc1.z, acc0.w + acc1.w);
    float dinv = 1.0f / fmaxf((float)(s1 - s0), 1.0f);

    float4 skip = *(const float4*)(base + 384 + c);
    float4 bs   = *(const float4*)(base + 512 + c);
    float4 gs   = *(const float4*)(base + 640 + c);

    float4 r;
    r.x = fmaxf(fmaf(gs.x, skip.x, bs.x), 0.f) + acc.x * dinv;
    r.y = fmaxf(fmaf(gs.y, skip.y, bs.y), 0.f) + acc.y * dinv;
    r.z = fmaxf(fmaf(gs.z, skip.z, bs.z), 0.f) + acc.z * dinv;
    r.w = fmaxf(fmaf(gs.w, skip.w, bs.w), 0.f) + acc.w * dinv;
    if (applyRelu) {
        r.x = fmaxf(r.x, 0.f);
        r.y = fmaxf(r.y, 0.f);
        r.z = fmaxf(r.z, 0.f);
        r.w = fmaxf(r.w, 0.f);
    }
    *(float4*)(xout + (size_t)warp * D + c) = r;
}

// ---------------- host launch ----------------
extern "C" void kernel_launch(void* const* d_in, const int* in_sizes, int n_in,
                              void* d_out, int out_size)
{
    const float* x_in    = (const float*)d_in[0];
    const void*  ei      = d_in[1];
    const float* W_lin   = (const float*)d_in[2];
    const float* W_film  = (const float*)d_in[3];
    const float* b_film  = (const float*)d_in[4];
    const float* W_skip  = (const float*)d_in[5];
    const float* W_fskip = (const float*)d_in[6];
    const int E = in_sizes[1] / 2;

    float *scratch, *x0, *x1;
    int *deg;
    cudaGetSymbolAddress((void**)&scratch, g_scratch);
    cudaGetSymbolAddress((void**)&x0, g_xbuf0);
    cudaGetSymbolAddress((void**)&x1, g_xbuf1);
    cudaGetSymbolAddress((void**)&deg, g_deg);

    const int NB = (N_NODES + 1023) / 1024;   // 98

    // ---- detect edge_index dtype, then build CSR by dst (once per launch) ----
    k_detect<<<1, 1>>>(ei, E);
    cudaMemsetAsync(deg, 0, N_NODES * sizeof(int), 0);
    k_deg<<<1024, 256>>>(ei, E);
    k_scan1<<<NB, 1024>>>();
    k_scan2<<<1, 1>>>(NB);
    k_scan3<<<NB, 1024>>>();
    k_scatter<<<1024, 256>>>(ei, E);

    float* out = (float*)d_out;
    const int MB = (N_NODES + BM - 1) / BM;   // 782

    for (int l = 0; l < NLAYERS; l++) {
        const float* A  = (l == 0) ? x_in : ((l % 2 == 0) ? x1 : x0);
        float*       xo = (l == NLAYERS - 1) ? out : ((l % 2 == 0) ? x0 : x1);

        gemm_kernel<<<dim3(MB, 2), 256>>>(A, W_lin   + (size_t)l * D * D,   nullptr,           scratch, N_NODES, 128, 0);
        gemm_kernel<<<dim3(MB, 4), 256>>>(A, W_film  + (size_t)l * D * 256, b_film + l * 256,  scratch, N_NODES, 256, 128);
        gemm_kernel<<<dim3(MB, 2), 256>>>(A, W_skip  + (size_t)l * D * D,   nullptr,           scratch, N_NODES, 128, 384);
        gemm_kernel<<<dim3(MB, 4), 256>>>(A, W_fskip + (size_t)l * D * 256, nullptr,           scratch, N_NODES, 256, 512);

        edge_agg_kernel<<<(N_NODES + 7) / 8, 256>>>(scratch, xo, l < NLAYERS - 1 ? 1 : 0);
    }
}

// round 5
// speedup vs baseline: 1.5793x; 1.5793x over previous
#include <cuda_runtime.h>
#include <cuda_bf16.h>
#include <cstdint>
#include <cstddef>

#define N_NODES 100000
#define N_EDGES_MAX 1600000
#define D 128
#define SLD 768            // scratch row: [h(0:128) | beta(128:256) | gamma(256:384) | skip(384:512) | beta_s(512:640) | gamma_s(640:768)]
#define NLAYERS 4

// ---------------- device scratch (no allocations allowed) ----------------
__device__ __align__(16) float g_scratch[(size_t)N_NODES * SLD];
__device__ __align__(16) float g_xbuf0[(size_t)N_NODES * D];
__device__ __align__(16) float g_xbuf1[(size_t)N_NODES * D];
__device__ int   g_deg[N_NODES];
__device__ int   g_off[N_NODES + 1];
__device__ int   g_cursor[N_NODES];
__device__ int   g_csr[N_EDGES_MAX];
__device__ int   g_bsum[128];
__device__ int   g_idx32;          // 1 => edge_index stored as int32, 0 => int64
// split weights: [L][768][128] bf16, n-major (k contiguous); bias [L][768]
__device__ __align__(16) __nv_bfloat16 g_wt_hi[NLAYERS * 768 * 128];
__device__ __align__(16) __nv_bfloat16 g_wt_lo[NLAYERS * 768 * 128];
__device__ __align__(16) float g_bias[NLAYERS * 768];

// ---------------- helpers ----------------
__device__ __forceinline__ uint32_t smem_u32(const void* p) {
    uint32_t a;
    asm("{ .reg .u64 t; cvta.to.shared.u64 t, %1; cvt.u32.u64 %0, t; }" : "=r"(a) : "l"(p));
    return a;
}

#define LDSM_X4(r, addr) \
    asm volatile("ldmatrix.sync.aligned.m8n8.x4.shared.b16 {%0,%1,%2,%3}, [%4];" \
                 : "=r"((r)[0]), "=r"((r)[1]), "=r"((r)[2]), "=r"((r)[3]) : "r"(addr))
#define LDSM_X2(r, addr) \
    asm volatile("ldmatrix.sync.aligned.m8n8.x2.shared.b16 {%0,%1}, [%2];" \
                 : "=r"((r)[0]), "=r"((r)[1]) : "r"(addr))

__device__ __forceinline__ void mma_bf16(float* c, const uint32_t* a, const uint32_t* b) {
    asm volatile("mma.sync.aligned.m16n8k16.row.col.f32.bf16.bf16.f32 "
                 "{%0,%1,%2,%3}, {%4,%5,%6,%7}, {%8,%9}, {%0,%1,%2,%3};"
                 : "+f"(c[0]), "+f"(c[1]), "+f"(c[2]), "+f"(c[3])
                 : "r"(a[0]), "r"(a[1]), "r"(a[2]), "r"(a[3]), "r"(b[0]), "r"(b[1]));
}

// ---------------- edge index dtype detection (JAX demotes int64->int32) ----------------
__global__ void k_detect(const void* __restrict__ ei, int E)
{
    const long long* p = (const long long*)ei;
    int n = E < 4096 ? E : 4096;
    int is32 = 0;
    for (int i = 0; i < n; i++) {
        long long v = p[i];
        if (v < 0 || v >= N_NODES) { is32 = 1; break; }
    }
    g_idx32 = is32;
}
__device__ __forceinline__ int load_edge(const void* ei, int idx, int mode)
{
    if (mode) return ((const int*)ei)[idx];
    return (int)((const long long*)ei)[idx];
}

// ---------------- weight prep: concat + transpose + bf16 hi/lo split ----------------
// Wt[l][n][k]: n<128 W_lin | 128..383 W_film | 384..511 W_skip | 512..767 W_fskip
__global__ void k_prep_weights(const float* __restrict__ W_lin, const float* __restrict__ W_film,
                               const float* __restrict__ b_film, const float* __restrict__ W_skip,
                               const float* __restrict__ W_fskip)
{
    const int total = NLAYERS * 768 * 128;
    for (int idx = blockIdx.x * blockDim.x + threadIdx.x; idx < total; idx += gridDim.x * blockDim.x) {
        int k = idx & 127;
        int n = (idx >> 7) % 768;
        int l = idx / (768 * 128);
        float v;
        if (n < 128)       v = W_lin[((size_t)l * 128 + k) * 128 + n];
        else if (n < 384)  v = W_film[((size_t)l * 128 + k) * 256 + (n - 128)];
        else if (n < 512)  v = W_skip[((size_t)l * 128 + k) * 128 + (n - 384)];
        else               v = W_fskip[((size_t)l * 128 + k) * 256 + (n - 512)];
        __nv_bfloat16 hi = __float2bfloat16(v);
        __nv_bfloat16 lo = __float2bfloat16(v - __bfloat162float(hi));
        g_wt_hi[idx] = hi;
        g_wt_lo[idx] = lo;
        if (k == 0)
            g_bias[l * 768 + n] = (n >= 128 && n < 384) ? b_film[l * 256 + (n - 128)] : 0.0f;
    }
}

// ---------------- HMMA GEMM: C[m0:m0+128, n0:n0+128] = A @ Wt^T (+bias), ld(C)=SLD ----------------
// bf16x3 split via mma.sync.m16n8k16 (baseline PTX, valid at compute_100).
// SMEM pitch 136 bf16 (272B): ldmatrix 8-row stride = 68 words -> banks 0,4,..,28, conflict-free.
#define PITCHB 272                       // bytes per smem row (136 bf16)
#define SM_AHI 0
#define SM_ALO (128 * PITCHB)            // 34816
#define SM_BHI (2 * 128 * PITCHB)        // 69632
#define SM_BLO (3 * 128 * PITCHB)        // 104448
#define SMEM_HM (4 * 128 * PITCHB + 16)  // 139280

__global__ __launch_bounds__(256, 1)
void hmma_gemm(const float* __restrict__ A, const __nv_bfloat16* __restrict__ Whi,
               const __nv_bfloat16* __restrict__ Wlo, const float* __restrict__ bias,
               float* __restrict__ C, int M)
{
    extern __shared__ char smem[];
    const uint32_t sb = smem_u32(smem);

    const int tid  = threadIdx.x;
    const int wid  = tid >> 5;
    const int lane = tid & 31;
    const int m0 = blockIdx.x * 128;
    const int n0 = blockIdx.y * 128;
    const int wm = (wid >> 1) * 32;      // warp row offset (0..96)
    const int wn = (wid & 1) * 64;       // warp col offset (0 or 64)

    // ---- load A (128x128 fp32), split bf16 hi/lo into SMEM ----
    #pragma unroll
    for (int it = 0; it < 16; it++) {
        int idx = tid + it * 256;                 // 0..4095
        int row = idx >> 5;
        int kq  = (idx & 31) << 2;                // k multiple of 4
        float4 v = make_float4(0.f, 0.f, 0.f, 0.f);
        if (m0 + row < M)
            v = *(const float4*)(A + (size_t)(m0 + row) * D + kq);
        __nv_bfloat16 h0 = __float2bfloat16(v.x), h1 = __float2bfloat16(v.y),
                      h2 = __float2bfloat16(v.z), h3 = __float2bfloat16(v.w);
        __nv_bfloat16 l0 = __float2bfloat16(v.x - __bfloat162float(h0)),
                      l1 = __float2bfloat16(v.y - __bfloat162float(h1)),
                      l2 = __float2bfloat16(v.z - __bfloat162float(h2)),
                      l3 = __float2bfloat16(v.w - __bfloat162float(h3));
        uint32_t off = (uint32_t)(row * PITCHB + kq * 2);
        uint2 hp, lp;
        hp.x = (uint32_t)__bfloat16_as_ushort(h0) | ((uint32_t)__bfloat16_as_ushort(h1) << 16);
        hp.y = (uint32_t)__bfloat16_as_ushort(h2) | ((uint32_t)__bfloat16_as_ushort(h3) << 16);
        lp.x = (uint32_t)__bfloat16_as_ushort(l0) | ((uint32_t)__bfloat16_as_ushort(l1) << 16);
        lp.y = (uint32_t)__bfloat16_as_ushort(l2) | ((uint32_t)__bfloat16_as_ushort(l3) << 16);
        *(uint2*)(smem + SM_AHI + off) = hp;
        *(uint2*)(smem + SM_ALO + off) = lp;
    }

    // ---- load B hi/lo (128 n-rows x 128 k bf16) into SMEM ----
    #pragma unroll
    for (int it = 0; it < 8; it++) {
        int idx = tid + it * 256;                 // 0..2047
        int n  = idx >> 4;
        int k8 = (idx & 15) << 3;                 // k multiple of 8 (16B)
        size_t srci = (size_t)(n0 + n) * 128 + k8;
        uint32_t off = (uint32_t)(n * PITCHB + k8 * 2);
        *(uint4*)(smem + SM_BHI + off) = *(const uint4*)(Whi + srci);
        *(uint4*)(smem + SM_BLO + off) = *(const uint4*)(Wlo + srci);
    }
    __syncthreads();

    // ---- mainloop: 8 k-steps x (2 mtiles x 8 ntiles) x 3 mma ----
    float acc[2][8][4];
    #pragma unroll
    for (int mt = 0; mt < 2; mt++)
        #pragma unroll
        for (int nt = 0; nt < 8; nt++)
            #pragma unroll
            for (int j = 0; j < 4; j++) acc[mt][nt][j] = 0.f;

    // ldmatrix lane addressing
    const uint32_t aAddrH = sb + SM_AHI + (uint32_t)((wm + (lane & 15)) * PITCHB + ((lane >> 4) * 8) * 2);
    const uint32_t aAddrL = aAddrH + (SM_ALO - SM_AHI);
    const uint32_t bAddrH = sb + SM_BHI + (uint32_t)((wn + (lane & 7)) * PITCHB + (((lane >> 3) & 1) * 8) * 2);
    const uint32_t bAddrL = bAddrH + (SM_BLO - SM_BHI);

    #pragma unroll
    for (int kt = 0; kt < 8; kt++) {
        const uint32_t ko = kt * 32;              // 16 bf16 = 32 bytes per k-step
        uint32_t ah[2][4], al[2][4];
        #pragma unroll
        for (int mt = 0; mt < 2; mt++) {
            LDSM_X4(ah[mt], aAddrH + mt * 16 * PITCHB + ko);
            LDSM_X4(al[mt], aAddrL + mt * 16 * PITCHB + ko);
        }
        uint32_t bh[8][2], bl[8][2];
        #pragma unroll
        for (int nt = 0; nt < 8; nt++) {
            LDSM_X2(bh[nt], bAddrH + nt * 8 * PITCHB + ko);
            LDSM_X2(bl[nt], bAddrL + nt * 8 * PITCHB + ko);
        }
        #pragma unroll
        for (int mt = 0; mt < 2; mt++)
            #pragma unroll
            for (int nt = 0; nt < 8; nt++) {
                mma_bf16(acc[mt][nt], ah[mt], bh[nt]);
                mma_bf16(acc[mt][nt], ah[mt], bl[nt]);
                mma_bf16(acc[mt][nt], al[mt], bh[nt]);
            }
    }

    // ---- epilogue: scatter accumulators + bias to C (ld=SLD) ----
    const int r0 = lane >> 2;
    const int c0 = (lane & 3) * 2;
    #pragma unroll
    for (int mt = 0; mt < 2; mt++) {
        #pragma unroll
        for (int nt = 0; nt < 8; nt++) {
            int col = n0 + wn + nt * 8 + c0;
            float2 b2 = *(const float2*)(bias + col);
            #pragma unroll
            for (int p = 0; p < 2; p++) {
                int row = m0 + wm + mt * 16 + r0 + p * 8;
                if (row < M) {
                    float2 o;
                    o.x = acc[mt][nt][p * 2 + 0] + b2.x;
                    o.y = acc[mt][nt][p * 2 + 1] + b2.y;
                    *(float2*)(C + (size_t)row * SLD + col) = o;
                }
            }
        }
    }
}

// ---------------- graph setup kernels ----------------
__global__ void k_deg(const void* __restrict__ ei, int E)
{
    const int mode = g_idx32;
    for (int i = blockIdx.x * blockDim.x + threadIdx.x; i < E; i += gridDim.x * blockDim.x) {
        int d = load_edge(ei, E + i, mode);
        atomicAdd(&g_deg[d], 1);
    }
}

__global__ void k_scan1()
{
    __shared__ int s[1024];
    int tid = threadIdx.x;
    int i = blockIdx.x * 1024 + tid;
    s[tid] = (i < N_NODES) ? g_deg[i] : 0;
    __syncthreads();
    #pragma unroll
    for (int d = 512; d > 0; d >>= 1) {
        if (tid < d) s[tid] += s[tid + d];
        __syncthreads();
    }
    if (tid == 0) g_bsum[blockIdx.x] = s[0];
}

__global__ void k_scan2(int nb)
{
    int run = 0;
    for (int b = 0; b < nb; b++) {
        int v = g_bsum[b];
        g_bsum[b] = run;
        run += v;
    }
    g_off[N_NODES] = run;
}

__global__ void k_scan3()
{
    __shared__ int s[1024];
    int tid = threadIdx.x;
    int i = blockIdx.x * 1024 + tid;
    int v = (i < N_NODES) ? g_deg[i] : 0;
    s[tid] = v;
    __syncthreads();
    #pragma unroll
    for (int d = 1; d < 1024; d <<= 1) {
        int t = (tid >= d) ? s[tid - d] : 0;
        __syncthreads();
        s[tid] += t;
        __syncthreads();
    }
    int excl = s[tid] - v;
    int base = g_bsum[blockIdx.x];
    if (i < N_NODES) {
        g_off[i]    = base + excl;
        g_cursor[i] = base + excl;
    }
}

__global__ void k_scatter(const void* __restrict__ ei, int E)
{
    const int mode = g_idx32;
    for (int i = blockIdx.x * blockDim.x + threadIdx.x; i < E; i += gridDim.x * blockDim.x) {
        int d = load_edge(ei, E + i, mode);
        int s = load_edge(ei, i, mode);
        int pos = atomicAdd(&g_cursor[d], 1);
        g_csr[pos] = s;
    }
}

// ---------------- fused edge aggregation + FiLM-skip epilogue ----------------
__global__ __launch_bounds__(256)
void edge_agg_kernel(const float* __restrict__ scratch, float* __restrict__ xout, int applyRelu)
{
    int warp = (blockIdx.x * blockDim.x + threadIdx.x) >> 5;
    int lane = threadIdx.x & 31;
    if (warp >= N_NODES) return;

    const float* base = scratch + (size_t)warp * SLD;
    const int c = lane * 4;

    float4 beta  = *(const float4*)(base + 128 + c);
    float4 gamma = *(const float4*)(base + 256 + c);

    const int s0 = g_off[warp], s1 = g_off[warp + 1];
    float4 acc0 = make_float4(0.f, 0.f, 0.f, 0.f);
    float4 acc1 = make_float4(0.f, 0.f, 0.f, 0.f);

    int i = s0;
    for (; i + 2 <= s1; i += 2) {
        int sA = g_csr[i];
        int sB = g_csr[i + 1];
        float4 hA = __ldg((const float4*)(scratch + (size_t)sA * SLD + c));
        float4 hB = __ldg((const float4*)(scratch + (size_t)sB * SLD + c));
        acc0.x += fmaxf(fmaf(gamma.x, hA.x, beta.x), 0.f);
        acc0.y += fmaxf(fmaf(gamma.y, hA.y, beta.y), 0.f);
        acc0.z += fmaxf(fmaf(gamma.z, hA.z, beta.z), 0.f);
        acc0.w += fmaxf(fmaf(gamma.w, hA.w, beta.w), 0.f);
        acc1.x += fmaxf(fmaf(gamma.x, hB.x, beta.x), 0.f);
        acc1.y += fmaxf(fmaf(gamma.y, hB.y, beta.y), 0.f);
        acc1.z += fmaxf(fmaf(gamma.z, hB.z, beta.z), 0.f);
        acc1.w += fmaxf(fmaf(gamma.w, hB.w, beta.w), 0.f);
    }
    if (i < s1) {
        int sA = g_csr[i];
        float4 hA = __ldg((const float4*)(scratch + (size_t)sA * SLD + c));
        acc0.x += fmaxf(fmaf(gamma.x, hA.x, beta.x), 0.f);
        acc0.y += fmaxf(fmaf(gamma.y, hA.y, beta.y), 0.f);
        acc0.z += fmaxf(fmaf(gamma.z, hA.z, beta.z), 0.f);
        acc0.w += fmaxf(fmaf(gamma.w, hA.w, beta.w), 0.f);
    }
    float4 acc = make_float4(acc0.x + acc1.x, acc0.y + acc1.y,
                             acc0.z + acc1.z, acc0.w + acc1.w);
    float dinv = 1.0f / fmaxf((float)(s1 - s0), 1.0f);

    float4 skip = *(const float4*)(base + 384 + c);
    float4 bs   = *(const float4*)(base + 512 + c);
    float4 gs   = *(const float4*)(base + 640 + c);

    float4 r;
    r.x = fmaxf(fmaf(gs.x, skip.x, bs.x), 0.f) + acc.x * dinv;
    r.y = fmaxf(fmaf(gs.y, skip.y, bs.y), 0.f) + acc.y * dinv;
    r.z = fmaxf(fmaf(gs.z, skip.z, bs.z), 0.f) + acc.z * dinv;
    r.w = fmaxf(fmaf(gs.w, skip.w, bs.w), 0.f) + acc.w * dinv;
    if (applyRelu) {
        r.x = fmaxf(r.x, 0.f);
        r.y = fmaxf(r.y, 0.f);
        r.z = fmaxf(r.z, 0.f);
        r.w = fmaxf(r.w, 0.f);
    }
    *(float4*)(xout + (size_t)warp * D + c) = r;
}

// ---------------- host launch ----------------
extern "C" void kernel_launch(void* const* d_in, const int* in_sizes, int n_in,
                              void* d_out, int out_size)
{
    const float* x_in    = (const float*)d_in[0];
    const void*  ei      = d_in[1];
    const float* W_lin   = (const float*)d_in[2];
    const float* W_film  = (const float*)d_in[3];
    const float* b_film  = (const float*)d_in[4];
    const float* W_skip  = (const float*)d_in[5];
    const float* W_fskip = (const float*)d_in[6];
    const int E = in_sizes[1] / 2;

    float *scratch, *x0, *x1, *bias;
    int *deg;
    __nv_bfloat16 *whi, *wlo;
    cudaGetSymbolAddress((void**)&scratch, g_scratch);
    cudaGetSymbolAddress((void**)&x0, g_xbuf0);
    cudaGetSymbolAddress((void**)&x1, g_xbuf1);
    cudaGetSymbolAddress((void**)&deg, g_deg);
    cudaGetSymbolAddress((void**)&whi, g_wt_hi);
    cudaGetSymbolAddress((void**)&wlo, g_wt_lo);
    cudaGetSymbolAddress((void**)&bias, g_bias);

    cudaFuncSetAttribute(hmma_gemm, cudaFuncAttributeMaxDynamicSharedMemorySize, SMEM_HM);

    const int NB = (N_NODES + 1023) / 1024;   // 98

    // ---- detect edge dtype, prep weights, build CSR (once per launch) ----
    k_detect<<<1, 1>>>(ei, E);
    k_prep_weights<<<512, 256>>>(W_lin, W_film, b_film, W_skip, W_fskip);
    cudaMemsetAsync(deg, 0, N_NODES * sizeof(int), 0);
    k_deg<<<1024, 256>>>(ei, E);
    k_scan1<<<NB, 1024>>>();
    k_scan2<<<1, 1>>>(NB);
    k_scan3<<<NB, 1024>>>();
    k_scatter<<<1024, 256>>>(ei, E);

    float* out = (float*)d_out;
    const int MB = (N_NODES + 127) / 128;     // 782

    for (int l = 0; l < NLAYERS; l++) {
        const float* A  = (l == 0) ? x_in : ((l % 2 == 0) ? x1 : x0);
        float*       xo = (l == NLAYERS - 1) ? out : ((l % 2 == 0) ? x0 : x1);

        hmma_gemm<<<dim3(MB, 6), 256, SMEM_HM>>>(
            A, whi + (size_t)l * 768 * 128, wlo + (size_t)l * 768 * 128,
            bias + l * 768, scratch, N_NODES);

        edge_agg_kernel<<<(N_NODES + 7) / 8, 256>>>(scratch, xo, l < NLAYERS - 1 ? 1 : 0);
    }
}